// round 6
// baseline (speedup 1.0000x reference)
#include <cuda_runtime.h>
#include <cuda_fp16.h>

#define N_POINTS 1000000
#define GRID_D   128
#define CH       32
#define NVOX     (GRID_D * GRID_D * GRID_D)   // 2,097,152
#define NBUCKET  32768                        // 32x32x32 cells of 4^3 voxels

// fp16 voxel-major grid: one voxel's 32 channels = 64B contiguous.
__device__ __half g_feat_h[(size_t)NVOX * CH];
// sort scratch
__device__ int      g_hist[NBUCKET];
__device__ int      g_off[NBUCKET];
__device__ unsigned g_key_rank[N_POINTS];     // key<<17 | rank
__device__ float4   g_xs[N_POINTS];           // sorted (fx,fy,fz, bits(p))

__device__ __forceinline__ void point_f(const float* __restrict__ x, int p,
                                        float& fx, float& fy, float& fz) {
    fx = fmaf(__ldg(&x[3 * p + 0]), 6.4f, 63.5f);   // LO=-10,HI=10,W=128
    fy = fmaf(__ldg(&x[3 * p + 1]), 6.4f, 63.5f);
    fz = fmaf(__ldg(&x[3 * p + 2]), 6.4f, 63.5f);
}

__device__ __forceinline__ int key_of(float fx, float fy, float fz) {
    const int cx = min(max((int)floorf(fx), 0), GRID_D - 1);
    const int cy = min(max((int)floorf(fy), 0), GRID_D - 1);
    const int cz = min(max((int)floorf(fz), 0), GRID_D - 1);
    return (((cz >> 2) * 32) + (cy >> 2)) * 32 + (cx >> 2);
}

__global__ void zero_hist() {
    const int i = blockIdx.x * blockDim.x + threadIdx.x;
    if (i < NBUCKET) g_hist[i] = 0;
}

__global__ __launch_bounds__(512) void rank_kernel(const float* __restrict__ x) {
    const int p = blockIdx.x * blockDim.x + threadIdx.x;
    if (p >= N_POINTS) return;
    float fx, fy, fz; point_f(x, p, fx, fy, fz);
    const int key = key_of(fx, fy, fz);
    const unsigned r = atomicAdd(&g_hist[key], 1);
    g_key_rank[p] = ((unsigned)key << 17) | r;
}

// exclusive scan of 32768 counters; one block of 1024 threads, 32 each
__global__ __launch_bounds__(1024) void scan_kernel() {
    __shared__ int warp_sums[32];
    const int t = threadIdx.x, lane = t & 31, wid = t >> 5;
    int v[32], s = 0;
    #pragma unroll
    for (int k = 0; k < 32; ++k) { v[k] = g_hist[t * 32 + k]; s += v[k]; }
    int ss = s;
    #pragma unroll
    for (int o = 1; o < 32; o <<= 1) {
        int n = __shfl_up_sync(0xffffffff, ss, o);
        if (lane >= o) ss += n;
    }
    if (lane == 31) warp_sums[wid] = ss;
    __syncthreads();
    if (wid == 0) {
        int ws = warp_sums[lane];
        #pragma unroll
        for (int o = 1; o < 32; o <<= 1) {
            int n = __shfl_up_sync(0xffffffff, ws, o);
            if (lane >= o) ws += n;
        }
        warp_sums[lane] = ws;
    }
    __syncthreads();
    int run = (wid > 0 ? warp_sums[wid - 1] : 0) + (ss - s);
    #pragma unroll
    for (int k = 0; k < 32; ++k) { g_off[t * 32 + k] = run; run += v[k]; }
}

__global__ __launch_bounds__(512) void place_kernel(const float* __restrict__ x) {
    const int p = blockIdx.x * blockDim.x + threadIdx.x;
    if (p >= N_POINTS) return;
    const unsigned kr = g_key_rank[p];
    const int pos = g_off[kr >> 17] + (int)(kr & 0x1FFFFu);
    float fx, fy, fz; point_f(x, p, fx, fy, fz);
    g_xs[pos] = make_float4(fx, fy, fz, __int_as_float(p));
}

// ---------------------------------------------------------------------------
// transpose (C,V) fp32 -> (V,C) fp16. Streaming reads (__ldcs) keep the
// 256MB source out of L2 so the fp16 grid can stay resident.
// ---------------------------------------------------------------------------
__global__ __launch_bounds__(256) void transpose_feat(const float* __restrict__ feature) {
    __shared__ float tile[32 * 256];
    const int t  = threadIdx.x;
    const int s0 = blockIdx.x * 256;

    float4 v[8];
    #pragma unroll
    for (int r = 0; r < 8; ++r) {
        const int i  = r * 256 + t;
        const int ch = i >> 6;
        const int c4 = i & 63;
        v[r] = __ldcs(reinterpret_cast<const float4*>(
                  &feature[(size_t)ch * NVOX + s0 + c4 * 4]));
    }
    #pragma unroll
    for (int r = 0; r < 8; ++r) {
        const int i   = r * 256 + t;
        const int ch  = i >> 6;
        const int c4  = i & 63;
        const int col = (c4 * 4) ^ ((ch >> 2) * 4);
        *reinterpret_cast<float4*>(&tile[ch * 256 + col]) = v[r];
    }
    __syncthreads();

    #pragma unroll
    for (int r = 0; r < 4; ++r) {
        const int i   = r * 256 + t;
        const int vox = i >> 2;
        const int oct = i & 3;
        half2 h[4];
        #pragma unroll
        for (int kk = 0; kk < 4; ++kk) {
            const int ch0 = oct * 8 + kk * 2;
            const int ch1 = ch0 + 1;
            const float a = tile[ch0 * 256 + (vox ^ ((ch0 >> 2) * 4))];
            const float b = tile[ch1 * 256 + (vox ^ ((ch1 >> 2) * 4))];
            h[kk] = __floats2half2_rn(a, b);
        }
        uint4 o;
        o.x = *reinterpret_cast<unsigned*>(&h[0]);
        o.y = *reinterpret_cast<unsigned*>(&h[1]);
        o.z = *reinterpret_cast<unsigned*>(&h[2]);
        o.w = *reinterpret_cast<unsigned*>(&h[3]);
        *reinterpret_cast<uint4*>(&g_feat_h[(size_t)(s0 + vox) * CH + oct * 8]) = o;
    }
}

// ---------------------------------------------------------------------------
// gather over bucket-sorted coords. 4 lanes/point, 8 channels each.
// Coord reads coalesced (sorted float4). Output scatter-written with __stcs
// (full 128B lines, evict-first: don't pollute L2 holding the grid).
// ---------------------------------------------------------------------------
__global__ __launch_bounds__(256) void gather_trilinear(float* __restrict__ out) {
    const int tid = blockIdx.x * blockDim.x + threadIdx.x;
    const int i   = tid >> 2;
    const int q   = tid & 3;
    if (i >= N_POINTS) return;

    const float4 s = g_xs[i];
    const float fx = s.x, fy = s.y, fz = s.z;
    const int   p  = __float_as_int(s.w);

    const float x0f = floorf(fx), y0f = floorf(fy), z0f = floorf(fz);
    const float wx = fx - x0f, wy = fy - y0f, wz = fz - z0f;
    const int x0 = (int)x0f, y0 = (int)y0f, z0 = (int)z0f;

    float  w[8];
    size_t idx[8];
    #pragma unroll
    for (int c = 0; c < 8; ++c) {
        const int dx = c & 1, dy = (c >> 1) & 1, dz = (c >> 2) & 1;
        const int xi = x0 + dx, yi = y0 + dy, zi = z0 + dz;
        const bool vld = (xi >= 0) && (xi < GRID_D) &&
                         (yi >= 0) && (yi < GRID_D) &&
                         (zi >= 0) && (zi < GRID_D);
        const int cx = min(max(xi, 0), GRID_D - 1);
        const int cy = min(max(yi, 0), GRID_D - 1);
        const int cz = min(max(zi, 0), GRID_D - 1);
        const float wxt = dx ? wx : 1.0f - wx;
        const float wyt = dy ? wy : 1.0f - wy;
        const float wzt = dz ? wz : 1.0f - wz;
        w[c]   = vld ? (wxt * wyt * wzt) : 0.0f;
        idx[c] = ((size_t)((cz * GRID_D + cy) * GRID_D + cx)) * CH + q * 8;
    }

    uint4 cv[8];
    #pragma unroll
    for (int c = 0; c < 8; ++c)
        cv[c] = *reinterpret_cast<const uint4*>(&g_feat_h[idx[c]]);

    float acc[8] = {0.f, 0.f, 0.f, 0.f, 0.f, 0.f, 0.f, 0.f};
    #pragma unroll
    for (int c = 0; c < 8; ++c) {
        const unsigned u[4] = {cv[c].x, cv[c].y, cv[c].z, cv[c].w};
        #pragma unroll
        for (int kk = 0; kk < 4; ++kk) {
            const half2  h2 = *reinterpret_cast<const half2*>(&u[kk]);
            const float2 f2 = __half22float2(h2);
            acc[kk * 2 + 0] = fmaf(w[c], f2.x, acc[kk * 2 + 0]);
            acc[kk * 2 + 1] = fmaf(w[c], f2.y, acc[kk * 2 + 1]);
        }
    }

    float* op = out + (size_t)p * CH + q * 8;
    __stcs(reinterpret_cast<float4*>(op),     make_float4(acc[0], acc[1], acc[2], acc[3]));
    __stcs(reinterpret_cast<float4*>(op + 4), make_float4(acc[4], acc[5], acc[6], acc[7]));
}

extern "C" void kernel_launch(void* const* d_in, const int* in_sizes, int n_in,
                              void* d_out, int out_size) {
    const float* x       = (const float*)d_in[0];   // (N_POINTS, 3)
    const float* feature = (const float*)d_in[1];   // (32, 128, 128, 128)
    float*       out     = (float*)d_out;           // (N_POINTS, 32)

    zero_hist<<<(NBUCKET + 255) / 256, 256>>>();
    rank_kernel<<<(N_POINTS + 511) / 512, 512>>>(x);
    scan_kernel<<<1, 1024>>>();
    place_kernel<<<(N_POINTS + 511) / 512, 512>>>(x);

    transpose_feat<<<NVOX / 256, 256>>>(feature);

    gather_trilinear<<<(N_POINTS * 4 + 255) / 256, 256>>>(out);
}

// round 7
// speedup vs baseline: 1.2953x; 1.2953x over previous
#include <cuda_runtime.h>
#include <cuda_fp16.h>

#define N_POINTS 1000000
#define GRID_D   128
#define CH       32
#define NVOX     (GRID_D * GRID_D * GRID_D)   // 2,097,152

// Feature transposed to (D,H,W,C) in half: one voxel's 32 channels = 64B.
// 128 MB static array -> grid ~fits L2 (126 MB), gather mostly L2-served.
__device__ __half g_feat_h[(size_t)NVOX * CH];

// ---------------------------------------------------------------------------
// Kernel 1: transpose (C, V) fp32 -> (V, C) fp16.
// Block = 256 threads, tile = 256 voxels x 32 channels (32 KB smem fp32).
// Read:  8x LDG.128/thread coalesced, MLP=8. smem XOR-swizzled.
// Write: per thread 4x uint4 (8 halves = 8 channels of one voxel), coalesced.
// ---------------------------------------------------------------------------
__global__ __launch_bounds__(256) void transpose_feat(const float* __restrict__ feature) {
    __shared__ float tile[32 * 256];          // [ch][col], pitch 256 floats
    const int t  = threadIdx.x;
    const int s0 = blockIdx.x * 256;          // voxel tile start

    float4 v[8];
    #pragma unroll
    for (int r = 0; r < 8; ++r) {
        const int i  = r * 256 + t;
        const int ch = i >> 6;
        const int c4 = i & 63;
        v[r] = __ldg(reinterpret_cast<const float4*>(
                  &feature[(size_t)ch * NVOX + s0 + c4 * 4]));
    }
    #pragma unroll
    for (int r = 0; r < 8; ++r) {
        const int i   = r * 256 + t;
        const int ch  = i >> 6;
        const int c4  = i & 63;
        const int col = (c4 * 4) ^ ((ch >> 2) * 4);   // swizzled, float4-aligned
        *reinterpret_cast<float4*>(&tile[ch * 256 + col]) = v[r];
    }
    __syncthreads();

    #pragma unroll
    for (int r = 0; r < 4; ++r) {
        const int i   = r * 256 + t;          // 0..1023
        const int vox = i >> 2;               // 0..255
        const int oct = i & 3;                // which 8-channel octet
        half2 h[4];
        #pragma unroll
        for (int kk = 0; kk < 4; ++kk) {
            const int ch0 = oct * 8 + kk * 2;
            const int ch1 = ch0 + 1;
            const float a = tile[ch0 * 256 + (vox ^ ((ch0 >> 2) * 4))];
            const float b = tile[ch1 * 256 + (vox ^ ((ch1 >> 2) * 4))];
            h[kk] = __floats2half2_rn(a, b);
        }
        uint4 o;
        o.x = *reinterpret_cast<unsigned*>(&h[0]);
        o.y = *reinterpret_cast<unsigned*>(&h[1]);
        o.z = *reinterpret_cast<unsigned*>(&h[2]);
        o.w = *reinterpret_cast<unsigned*>(&h[3]);
        *reinterpret_cast<uint4*>(&g_feat_h[(size_t)(s0 + vox) * CH + oct * 8]) = o;
    }
}

// ---------------------------------------------------------------------------
// Kernel 2: trilinear gather. 4 lanes per point; each lane owns 8 channels
// (one 16B uint4 per corner). 8 independent corner loads -> MLP=8.
// Output written with __stcs (evict-first): write-once stream must not evict
// the L2-resident fp16 grid.
// ---------------------------------------------------------------------------
__global__ __launch_bounds__(256) void gather_trilinear(const float* __restrict__ x,
                                                        float* __restrict__ out) {
    const int tid = blockIdx.x * blockDim.x + threadIdx.x;
    const int p   = tid >> 2;                 // point index
    const int q   = tid & 3;                  // channel octet
    if (p >= N_POINTS) return;

    const float px = __ldg(&x[3 * p + 0]);
    const float py = __ldg(&x[3 * p + 1]);
    const float pz = __ldg(&x[3 * p + 2]);

    // fx = x*6.4 + 63.5  (LO=-10, HI=10, W=128)
    const float fx = fmaf(px, 6.4f, 63.5f);
    const float fy = fmaf(py, 6.4f, 63.5f);
    const float fz = fmaf(pz, 6.4f, 63.5f);

    const float x0f = floorf(fx), y0f = floorf(fy), z0f = floorf(fz);
    const float wx = fx - x0f, wy = fy - y0f, wz = fz - z0f;
    const int x0 = (int)x0f, y0 = (int)y0f, z0 = (int)z0f;

    float  w[8];
    size_t idx[8];
    #pragma unroll
    for (int c = 0; c < 8; ++c) {
        const int dx = c & 1, dy = (c >> 1) & 1, dz = (c >> 2) & 1;
        const int xi = x0 + dx, yi = y0 + dy, zi = z0 + dz;
        const bool vld = (xi >= 0) && (xi < GRID_D) &&
                         (yi >= 0) && (yi < GRID_D) &&
                         (zi >= 0) && (zi < GRID_D);
        const int cx = min(max(xi, 0), GRID_D - 1);
        const int cy = min(max(yi, 0), GRID_D - 1);
        const int cz = min(max(zi, 0), GRID_D - 1);
        const float wxt = dx ? wx : 1.0f - wx;
        const float wyt = dy ? wy : 1.0f - wy;
        const float wzt = dz ? wz : 1.0f - wz;
        w[c]   = vld ? (wxt * wyt * wzt) : 0.0f;
        idx[c] = ((size_t)((cz * GRID_D + cy) * GRID_D + cx)) * CH + q * 8;
    }

    uint4 cv[8];
    #pragma unroll
    for (int c = 0; c < 8; ++c)
        cv[c] = *reinterpret_cast<const uint4*>(&g_feat_h[idx[c]]);

    float acc[8] = {0.f, 0.f, 0.f, 0.f, 0.f, 0.f, 0.f, 0.f};
    #pragma unroll
    for (int c = 0; c < 8; ++c) {
        const unsigned u[4] = {cv[c].x, cv[c].y, cv[c].z, cv[c].w};
        #pragma unroll
        for (int kk = 0; kk < 4; ++kk) {
            const half2  h2 = *reinterpret_cast<const half2*>(&u[kk]);
            const float2 f2 = __half22float2(h2);
            acc[kk * 2 + 0] = fmaf(w[c], f2.x, acc[kk * 2 + 0]);
            acc[kk * 2 + 1] = fmaf(w[c], f2.y, acc[kk * 2 + 1]);
        }
    }

    float* op = out + (size_t)p * CH + q * 8;
    __stcs(reinterpret_cast<float4*>(op),     make_float4(acc[0], acc[1], acc[2], acc[3]));
    __stcs(reinterpret_cast<float4*>(op + 4), make_float4(acc[4], acc[5], acc[6], acc[7]));
}

extern "C" void kernel_launch(void* const* d_in, const int* in_sizes, int n_in,
                              void* d_out, int out_size) {
    const float* x       = (const float*)d_in[0];   // (N_POINTS, 3)
    const float* feature = (const float*)d_in[1];   // (32, 128, 128, 128)
    float*       out     = (float*)d_out;           // (N_POINTS, 32)

    transpose_feat<<<NVOX / 256, 256>>>(feature);

    const int total = N_POINTS * 4;
    gather_trilinear<<<(total + 255) / 256, 256>>>(x, out);
}

// round 8
// speedup vs baseline: 1.3198x; 1.0189x over previous
#include <cuda_runtime.h>
#include <cuda_fp16.h>

#define N_POINTS 1000000
#define GRID_D   128
#define CH       32
#define CHP      16                            // channels per pass
#define NVOX     (GRID_D * GRID_D * GRID_D)    // 2,097,152

// Two 64MB fp16 half-grids, voxel-major: [pass][vox][16ch].
// Each pass's working set (64MB) fits L2 (126MB) with headroom.
__device__ __half g_feat_h[2 * (size_t)NVOX * CHP];

// ---------------------------------------------------------------------------
// Transpose one 16-channel half: (16ch, V) fp32 -> (V, 16ch) fp16.
// Block = 256 threads, tile = 256 voxels x 16 channels (16KB smem).
// Read:  4x LDG.128/thread (__ldcs: don't pollute L2), coalesced, MLP=4.
// smem:  col = base ^ (((ch>>3)&1)*16) -> store uniform-xor (conflict-free),
//        read oct0->banks 0..15, oct1->banks 16..31 (disjoint).
// Write: 2x uint4/thread (8 halves = 8 channels of one voxel), coalesced.
// ---------------------------------------------------------------------------
__global__ __launch_bounds__(256) void transpose_half(const float* __restrict__ feature,
                                                      int pass) {
    __shared__ float tile[CHP * 256];
    const int t  = threadIdx.x;
    const int s0 = blockIdx.x * 256;
    const int ch_base = pass * CHP;
    __half* dst = g_feat_h + (size_t)pass * NVOX * CHP;

    float4 v[4];
    #pragma unroll
    for (int r = 0; r < 4; ++r) {
        const int i  = r * 256 + t;            // 0..1023 float4 slots
        const int ch = i >> 6;                 // 0..15
        const int c4 = i & 63;
        v[r] = __ldcs(reinterpret_cast<const float4*>(
                  &feature[(size_t)(ch_base + ch) * NVOX + s0 + c4 * 4]));
    }
    #pragma unroll
    for (int r = 0; r < 4; ++r) {
        const int i   = r * 256 + t;
        const int ch  = i >> 6;
        const int c4  = i & 63;
        const int col = (c4 * 4) ^ (((ch >> 3) & 1) * 16);
        *reinterpret_cast<float4*>(&tile[ch * 256 + col]) = v[r];
    }
    __syncthreads();

    #pragma unroll
    for (int r = 0; r < 2; ++r) {
        const int i   = r * 256 + t;           // 0..511 output uint4 slots
        const int vox = i >> 1;                // 0..255
        const int oct = i & 1;                 // which 8-channel octet
        half2 h[4];
        #pragma unroll
        for (int kk = 0; kk < 4; ++kk) {
            const int ch0 = oct * 8 + kk * 2;
            const int ch1 = ch0 + 1;
            const int s   = ((ch0 >> 3) & 1) * 16;   // same for ch1
            const float a = tile[ch0 * 256 + (vox ^ s)];
            const float b = tile[ch1 * 256 + (vox ^ s)];
            h[kk] = __floats2half2_rn(a, b);
        }
        uint4 o;
        o.x = *reinterpret_cast<unsigned*>(&h[0]);
        o.y = *reinterpret_cast<unsigned*>(&h[1]);
        o.z = *reinterpret_cast<unsigned*>(&h[2]);
        o.w = *reinterpret_cast<unsigned*>(&h[3]);
        *reinterpret_cast<uint4*>(&dst[(size_t)(s0 + vox) * CHP + oct * 8]) = o;
    }
}

// ---------------------------------------------------------------------------
// Gather one 16-channel half. 2 lanes/point; each lane owns 8 channels
// (16B uint4 per corner). 8 corner loads batched -> MLP=8. Grid half is
// L2-warm from the preceding transpose launch.
// ---------------------------------------------------------------------------
__global__ __launch_bounds__(256) void gather_half(const float* __restrict__ x,
                                                   float* __restrict__ out,
                                                   int pass) {
    const int tid = blockIdx.x * blockDim.x + threadIdx.x;
    const int p   = tid >> 1;                  // point index
    const int q   = tid & 1;                   // octet within this half
    if (p >= N_POINTS) return;
    const __half* grid = g_feat_h + (size_t)pass * NVOX * CHP;

    const float px = __ldg(&x[3 * p + 0]);
    const float py = __ldg(&x[3 * p + 1]);
    const float pz = __ldg(&x[3 * p + 2]);

    // fx = x*6.4 + 63.5  (LO=-10, HI=10, W=128)
    const float fx = fmaf(px, 6.4f, 63.5f);
    const float fy = fmaf(py, 6.4f, 63.5f);
    const float fz = fmaf(pz, 6.4f, 63.5f);

    const float x0f = floorf(fx), y0f = floorf(fy), z0f = floorf(fz);
    const float wx = fx - x0f, wy = fy - y0f, wz = fz - z0f;
    const int x0 = (int)x0f, y0 = (int)y0f, z0 = (int)z0f;

    float  w[8];
    size_t idx[8];
    #pragma unroll
    for (int c = 0; c < 8; ++c) {
        const int dx = c & 1, dy = (c >> 1) & 1, dz = (c >> 2) & 1;
        const int xi = x0 + dx, yi = y0 + dy, zi = z0 + dz;
        const bool vld = (xi >= 0) && (xi < GRID_D) &&
                         (yi >= 0) && (yi < GRID_D) &&
                         (zi >= 0) && (zi < GRID_D);
        const int cx = min(max(xi, 0), GRID_D - 1);
        const int cy = min(max(yi, 0), GRID_D - 1);
        const int cz = min(max(zi, 0), GRID_D - 1);
        const float wxt = dx ? wx : 1.0f - wx;
        const float wyt = dy ? wy : 1.0f - wy;
        const float wzt = dz ? wz : 1.0f - wz;
        w[c]   = vld ? (wxt * wyt * wzt) : 0.0f;
        idx[c] = ((size_t)((cz * GRID_D + cy) * GRID_D + cx)) * CHP + q * 8;
    }

    uint4 cv[8];
    #pragma unroll
    for (int c = 0; c < 8; ++c)
        cv[c] = *reinterpret_cast<const uint4*>(&grid[idx[c]]);

    float acc[8] = {0.f, 0.f, 0.f, 0.f, 0.f, 0.f, 0.f, 0.f};
    #pragma unroll
    for (int c = 0; c < 8; ++c) {
        const unsigned u[4] = {cv[c].x, cv[c].y, cv[c].z, cv[c].w};
        #pragma unroll
        for (int kk = 0; kk < 4; ++kk) {
            const half2  h2 = *reinterpret_cast<const half2*>(&u[kk]);
            const float2 f2 = __half22float2(h2);
            acc[kk * 2 + 0] = fmaf(w[c], f2.x, acc[kk * 2 + 0]);
            acc[kk * 2 + 1] = fmaf(w[c], f2.y, acc[kk * 2 + 1]);
        }
    }

    float* op = out + (size_t)p * CH + pass * CHP + q * 8;
    __stcs(reinterpret_cast<float4*>(op),     make_float4(acc[0], acc[1], acc[2], acc[3]));
    __stcs(reinterpret_cast<float4*>(op + 4), make_float4(acc[4], acc[5], acc[6], acc[7]));
}

extern "C" void kernel_launch(void* const* d_in, const int* in_sizes, int n_in,
                              void* d_out, int out_size) {
    const float* x       = (const float*)d_in[0];   // (N_POINTS, 3)
    const float* feature = (const float*)d_in[1];   // (32, 128, 128, 128)
    float*       out     = (float*)d_out;           // (N_POINTS, 32)

    const int gblocks = (N_POINTS * 2 + 255) / 256;

    // pass 0: channels 0..15 — gather runs while its half-grid is L2-warm
    transpose_half<<<NVOX / 256, 256>>>(feature, 0);
    gather_half<<<gblocks, 256>>>(x, out, 0);

    // pass 1: channels 16..31
    transpose_half<<<NVOX / 256, 256>>>(feature, 1);
    gather_half<<<gblocks, 256>>>(x, out, 1);
}